// round 1
// baseline (speedup 1.0000x reference)
#include <cuda_runtime.h>

#define NN 500000
#define FD 128
#define HD 256
#define CD 40

// ---------------- scratch (device globals; no allocation allowed) ----------
__device__ int   g_first_pos[NN];
__device__ int   g_rank[NN];
__device__ int   g_mapped[NN];
__device__ int   g_blocksum[1024];
__device__ int   g_blockoff[1024];
__device__ float g_agg[(size_t)NN * HD];   // 512 MB segment-sum accumulator

// ---------------- init ------------------------------------------------------
__global__ void k_zero_agg() {
    size_t n4 = (size_t)NN * HD / 4;
    float4 z = make_float4(0.f, 0.f, 0.f, 0.f);
    float4* p = (float4*)g_agg;
    for (size_t i = (size_t)blockIdx.x * blockDim.x + threadIdx.x; i < n4;
         i += (size_t)gridDim.x * blockDim.x)
        p[i] = z;
}

__global__ void k_init_first() {
    int i = blockIdx.x * blockDim.x + threadIdx.x;
    if (i < NN) g_first_pos[i] = NN;
}

// first_pos[v] = min i with seg[i]==v
__global__ void k_firstpos(const int* __restrict__ edge) {
    int i = blockIdx.x * blockDim.x + threadIdx.x;
    if (i < NN) atomicMin(&g_first_pos[edge[2 * i]], i);
}

// ---------------- prefix-scan of first-occurrence flags ---------------------
// pass 1: per-block (1024 elems) flag sums
__global__ void k_scan1(const int* __restrict__ edge) {
    __shared__ int wsum[8];
    int b = blockIdx.x, tid = threadIdx.x;
    int base = b * 1024 + tid * 4;
    int s = 0;
#pragma unroll
    for (int j = 0; j < 4; j++) {
        int i = base + j;
        if (i < NN) s += (g_first_pos[edge[2 * i]] == i);
    }
    for (int o = 16; o > 0; o >>= 1) s += __shfl_down_sync(0xffffffffu, s, o);
    if ((tid & 31) == 0) wsum[tid >> 5] = s;
    __syncthreads();
    if (tid == 0) {
        int t = 0;
#pragma unroll
        for (int w = 0; w < 8; w++) t += wsum[w];
        g_blocksum[b] = t;
    }
}

// pass 2: exclusive scan of block sums (nb <= 512), single block of 512
__global__ void k_scan2(int nb) {
    __shared__ int sm[512];
    int t = threadIdx.x;
    int v = (t < nb) ? g_blocksum[t] : 0;
    sm[t] = v;
    __syncthreads();
    for (int o = 1; o < 512; o <<= 1) {
        int add = (t >= o) ? sm[t - o] : 0;
        __syncthreads();
        sm[t] += add;
        __syncthreads();
    }
    if (t < nb) g_blockoff[t] = sm[t] - v;
}

// pass 3: full exclusive positions -> rank[seg[i]] at first occurrences
__global__ void k_scan3(const int* __restrict__ edge) {
    __shared__ int wsum[8];
    int b = blockIdx.x, tid = threadIdx.x;
    int lane = tid & 31, w = tid >> 5;
    int base = b * 1024 + tid * 4;
    int f[4], segv[4];
    int t = 0;
#pragma unroll
    for (int j = 0; j < 4; j++) {
        int i = base + j;
        int fj = 0, sv = 0;
        if (i < NN) { sv = edge[2 * i]; fj = (g_first_pos[sv] == i); }
        f[j] = fj; segv[j] = sv; t += fj;
    }
    int incl = t;
    for (int o = 1; o < 32; o <<= 1) {
        int u = __shfl_up_sync(0xffffffffu, incl, o);
        if (lane >= o) incl += u;
    }
    if (lane == 31) wsum[w] = incl;
    __syncthreads();
    int woff = 0;
    for (int ww = 0; ww < w; ww++) woff += wsum[ww];
    int run = g_blockoff[b] + woff + (incl - t);
#pragma unroll
    for (int j = 0; j < 4; j++) {
        if (f[j]) { g_rank[segv[j]] = run; run++; }
    }
}

// mapped[i] = rank[ seg[seg[i]] ]
__global__ void k_mapped(const int* __restrict__ edge) {
    int i = blockIdx.x * blockDim.x + threadIdx.x;
    if (i < NN) {
        int s = edge[2 * i];
        int v = edge[2 * s];
        g_mapped[i] = g_rank[v];
    }
}

// ---------------- GEMM1 (x@W1+b1, relu) fused with atomic scatter ----------
// tile: 64 rows x 256 cols, K=128 in chunks of 16; 256 thr, 8x8 per thread
__global__ void __launch_bounds__(256, 2) k_gemm1_scatter(
    const float* __restrict__ x, const float* __restrict__ W1,
    const float* __restrict__ b1)
{
    __shared__ float Xs[16][65];     // [k][row], padded
    __shared__ float Ws[16][256];    // [k][col]
    int tid = threadIdx.x;
    int tx = tid & 31;               // col group: cols tx*8..tx*8+7
    int ty = tid >> 5;               // row group: rows ty*8..ty*8+7
    int rowBase = blockIdx.x * 64;

    float acc[8][8];
#pragma unroll
    for (int r = 0; r < 8; r++)
#pragma unroll
        for (int c = 0; c < 8; c++) acc[r][c] = 0.f;

    int lr = tid >> 2;               // load row 0..63
    int lk = (tid & 3) * 4;          // load k quarter
    int grow = rowBase + lr;
    const float* xrow = x + (size_t)grow * FD;

    for (int k0 = 0; k0 < FD; k0 += 16) {
        float4 xv = make_float4(0.f, 0.f, 0.f, 0.f);
        if (grow < NN) xv = *(const float4*)(xrow + k0 + lk);
        Xs[lk + 0][lr] = xv.x; Xs[lk + 1][lr] = xv.y;
        Xs[lk + 2][lr] = xv.z; Xs[lk + 3][lr] = xv.w;
#pragma unroll
        for (int j = 0; j < 4; j++) {
            int e4 = tid + j * 256;
            int kk = e4 >> 6;
            int c4 = (e4 & 63) << 2;
            *(float4*)&Ws[kk][c4] = *(const float4*)(W1 + (size_t)(k0 + kk) * HD + c4);
        }
        __syncthreads();
#pragma unroll
        for (int k = 0; k < 16; k++) {
            float a[8];
#pragma unroll
            for (int r = 0; r < 8; r++) a[r] = Xs[k][ty * 8 + r];
            float4 b0 = *(float4*)&Ws[k][tx * 8];
            float4 b1v = *(float4*)&Ws[k][tx * 8 + 4];
            float bb[8] = {b0.x, b0.y, b0.z, b0.w, b1v.x, b1v.y, b1v.z, b1v.w};
#pragma unroll
            for (int r = 0; r < 8; r++)
#pragma unroll
                for (int c = 0; c < 8; c++)
                    acc[r][c] = fmaf(a[r], bb[c], acc[r][c]);
        }
        __syncthreads();
    }

    float bias[8];
#pragma unroll
    for (int c = 0; c < 8; c++) bias[c] = b1[tx * 8 + c];
#pragma unroll
    for (int r = 0; r < 8; r++) {
        int row = rowBase + ty * 8 + r;
        if (row < NN) {
            int m = g_mapped[row];
            float* dst = g_agg + (size_t)m * HD + tx * 8;
#pragma unroll
            for (int c = 0; c < 8; c++) {
                float v = acc[r][c] + bias[c];
                v = v > 0.f ? v : 0.f;
                atomicAdd(dst + c, v);
            }
        }
    }
}

// ---------------- GEMM2: out = relu(agg) @ W2 + b2 --------------------------
// tile: 128 rows x 40 cols, K=256 in chunks of 16; 256 thr, 4x5 per thread
// static smem: W2s 256*40*4 = 40960 B, As 128*16*4 = 8192 B -> 49152 B total
__global__ void __launch_bounds__(256) k_gemm2(
    const float* __restrict__ W2, const float* __restrict__ b2,
    float* __restrict__ out)
{
    __shared__ float W2s[256 * 40];
    __shared__ float As[128][16];    // [row][k-chunk]
    int tid = threadIdx.x;
    int tx = tid & 7;                // cols tx + 8*c, c<5
    int ty = tid >> 3;               // rows ty*4..ty*4+3
    int row0 = blockIdx.x * 128;

    for (int e = tid; e < 256 * 40; e += 256) W2s[e] = W2[e];

    float acc[4][5];
#pragma unroll
    for (int r = 0; r < 4; r++)
#pragma unroll
        for (int c = 0; c < 5; c++) acc[r][c] = 0.f;

    for (int k0 = 0; k0 < HD; k0 += 16) {
        __syncthreads();             // covers W2 load (1st iter) + As reuse
        // load 128x16 agg chunk with relu, 2 float4 per thread
#pragma unroll
        for (int j = 0; j < 2; j++) {
            int e4 = tid + j * 256;   // 0..511 float4 indices (128*16/4)
            int r = e4 >> 2;          // 4 float4 per row
            int kq = (e4 & 3) << 2;
            int row = row0 + r;
            float4 v = make_float4(0.f, 0.f, 0.f, 0.f);
            if (row < NN) v = *(const float4*)(g_agg + (size_t)row * HD + k0 + kq);
            As[r][kq + 0] = fmaxf(v.x, 0.f);
            As[r][kq + 1] = fmaxf(v.y, 0.f);
            As[r][kq + 2] = fmaxf(v.z, 0.f);
            As[r][kq + 3] = fmaxf(v.w, 0.f);
        }
        __syncthreads();
#pragma unroll
        for (int k = 0; k < 16; k++) {
            float a[4], w[5];
#pragma unroll
            for (int r = 0; r < 4; r++) a[r] = As[ty * 4 + r][k];
#pragma unroll
            for (int c = 0; c < 5; c++) w[c] = W2s[(k0 + k) * 40 + tx + 8 * c];
#pragma unroll
            for (int r = 0; r < 4; r++)
#pragma unroll
                for (int c = 0; c < 5; c++)
                    acc[r][c] = fmaf(a[r], w[c], acc[r][c]);
        }
    }

    float bb[5];
#pragma unroll
    for (int c = 0; c < 5; c++) bb[c] = b2[tx + 8 * c];
#pragma unroll
    for (int r = 0; r < 4; r++) {
        int row = row0 + ty * 4 + r;
        if (row < NN) {
#pragma unroll
            for (int c = 0; c < 5; c++)
                out[(size_t)row * CD + tx + 8 * c] = acc[r][c] + bb[c];
        }
    }
}

// ---------------- launch -----------------------------------------------------
extern "C" void kernel_launch(void* const* d_in, const int* in_sizes, int n_in,
                              void* d_out, int out_size) {
    const float* x    = (const float*)d_in[0];
    const int*   edge = (const int*)d_in[1];
    const float* W1   = (const float*)d_in[2];
    const float* b1   = (const float*)d_in[3];
    const float* W2   = (const float*)d_in[4];
    const float* b2   = (const float*)d_in[5];
    float* out = (float*)d_out;

    int nb_elem = (NN + 255) / 256;          // 1954
    int nb_scan = (NN + 1023) / 1024;        // 489
    int nb_g1   = (NN + 63) / 64;            // 7813
    int nb_g2   = (NN + 127) / 128;          // 3907

    k_zero_agg<<<8192, 256>>>();
    k_init_first<<<nb_elem, 256>>>();
    k_firstpos<<<nb_elem, 256>>>(edge);
    k_scan1<<<nb_scan, 256>>>(edge);
    k_scan2<<<1, 512>>>(nb_scan);
    k_scan3<<<nb_scan, 256>>>(edge);
    k_mapped<<<nb_elem, 256>>>(edge);
    k_gemm1_scatter<<<nb_g1, 256>>>(x, W1, b1);
    k_gemm2<<<nb_g2, 256>>>(W2, b2, out);
}

// round 2
// speedup vs baseline: 1.3107x; 1.3107x over previous
#include <cuda_runtime.h>

#define NN 500000
#define FD 128
#define HD 256
#define CD 40

// ---------------- scratch (device globals; no allocation allowed) ----------
__device__ int   g_first_pos[NN];
__device__ int   g_rank[NN];
__device__ int   g_mapped[NN];
__device__ int   g_blocksum[1024];
__device__ int   g_blockoff[1024];
__device__ float g_agg[(size_t)NN * HD];   // 512 MB segment-sum accumulator

// ---------------- helpers ----------------------------------------------------
__device__ __forceinline__ unsigned f2tf(float f) {
    unsigned u;
    asm volatile("cvt.rna.tf32.f32 %0, %1;" : "=r"(u) : "f"(f));
    return u;
}
__device__ __forceinline__ void cp_async16(unsigned s, const void* g) {
    asm volatile("cp.async.cg.shared.global [%0], [%1], 16;" :: "r"(s), "l"(g));
}
__device__ __forceinline__ void cp_commit() {
    asm volatile("cp.async.commit_group;");
}
template <int N>
__device__ __forceinline__ void cp_wait() {
    asm volatile("cp.async.wait_group %0;" :: "n"(N));
}
__device__ __forceinline__ void mma_tf32(float* c, const unsigned* a,
                                         unsigned b0, unsigned b1) {
    asm volatile(
        "mma.sync.aligned.m16n8k8.row.col.f32.tf32.tf32.f32 "
        "{%0,%1,%2,%3}, {%4,%5,%6,%7}, {%8,%9}, {%0,%1,%2,%3};\n"
        : "+f"(c[0]), "+f"(c[1]), "+f"(c[2]), "+f"(c[3])
        : "r"(a[0]), "r"(a[1]), "r"(a[2]), "r"(a[3]), "r"(b0), "r"(b1));
}

// ---------------- init ------------------------------------------------------
__global__ void k_zero_agg() {
    size_t n4 = (size_t)NN * HD / 4;
    float4 z = make_float4(0.f, 0.f, 0.f, 0.f);
    float4* p = (float4*)g_agg;
    for (size_t i = (size_t)blockIdx.x * blockDim.x + threadIdx.x; i < n4;
         i += (size_t)gridDim.x * blockDim.x)
        p[i] = z;
}

__global__ void k_init_first() {
    int i = blockIdx.x * blockDim.x + threadIdx.x;
    if (i < NN) g_first_pos[i] = NN;
}

__global__ void k_firstpos(const int* __restrict__ edge) {
    int i = blockIdx.x * blockDim.x + threadIdx.x;
    if (i < NN) {
        int s = ((const int2*)edge)[i].x;
        atomicMin(&g_first_pos[s], i);
    }
}

// ---------------- prefix-scan of first-occurrence flags ---------------------
__global__ void k_scan1(const int* __restrict__ edge) {
    __shared__ int wsum[8];
    int b = blockIdx.x, tid = threadIdx.x;
    int base = b * 1024 + tid * 4;
    int s = 0;
#pragma unroll
    for (int j = 0; j < 4; j++) {
        int i = base + j;
        if (i < NN) s += (g_first_pos[((const int2*)edge)[i].x] == i);
    }
    for (int o = 16; o > 0; o >>= 1) s += __shfl_down_sync(0xffffffffu, s, o);
    if ((tid & 31) == 0) wsum[tid >> 5] = s;
    __syncthreads();
    if (tid == 0) {
        int t = 0;
#pragma unroll
        for (int w = 0; w < 8; w++) t += wsum[w];
        g_blocksum[b] = t;
    }
}

__global__ void k_scan2(int nb) {
    __shared__ int sm[512];
    int t = threadIdx.x;
    int v = (t < nb) ? g_blocksum[t] : 0;
    sm[t] = v;
    __syncthreads();
    for (int o = 1; o < 512; o <<= 1) {
        int add = (t >= o) ? sm[t - o] : 0;
        __syncthreads();
        sm[t] += add;
        __syncthreads();
    }
    if (t < nb) g_blockoff[t] = sm[t] - v;
}

__global__ void k_scan3(const int* __restrict__ edge) {
    __shared__ int wsum[8];
    int b = blockIdx.x, tid = threadIdx.x;
    int lane = tid & 31, w = tid >> 5;
    int base = b * 1024 + tid * 4;
    int f[4], segv[4];
    int t = 0;
#pragma unroll
    for (int j = 0; j < 4; j++) {
        int i = base + j;
        int fj = 0, sv = 0;
        if (i < NN) { sv = ((const int2*)edge)[i].x; fj = (g_first_pos[sv] == i); }
        f[j] = fj; segv[j] = sv; t += fj;
    }
    int incl = t;
    for (int o = 1; o < 32; o <<= 1) {
        int u = __shfl_up_sync(0xffffffffu, incl, o);
        if (lane >= o) incl += u;
    }
    if (lane == 31) wsum[w] = incl;
    __syncthreads();
    int woff = 0;
    for (int ww = 0; ww < w; ww++) woff += wsum[ww];
    int run = g_blockoff[b] + woff + (incl - t);
#pragma unroll
    for (int j = 0; j < 4; j++) {
        if (f[j]) { g_rank[segv[j]] = run; run++; }
    }
}

// mapped[i] = rank[ seg[seg[i]] ]
__global__ void k_mapped(const int* __restrict__ edge) {
    int i = blockIdx.x * blockDim.x + threadIdx.x;
    if (i < NN) {
        int s = ((const int2*)edge)[i].x;
        int v = __ldg(edge + 2 * (size_t)s);
        g_mapped[i] = g_rank[v];
    }
}

// ---------------- GEMM1 (tf32 mma) fused with atomic scatter ----------------
// block tile 128x128, 8 warps (4x2), warp tile 32x64, BK=16, double-buffered.
#define BM 128
#define BN 128
#define BK 16
#define XS_S 20     // A smem row stride (conflict-free for frag loads)
#define WS_S 136    // B smem row stride (conflict-free for frag loads)

__global__ void __launch_bounds__(256, 2) k_gemm1_mma(
    const float* __restrict__ x, const float* __restrict__ W1,
    const float* __restrict__ b1)
{
    __shared__ unsigned Xs[2][BM][XS_S];   // 20480 B
    __shared__ unsigned Ws[2][BK][WS_S];   // 17408 B

    int tid = threadIdx.x;
    int lane = tid & 31;
    int wid = tid >> 5;
    int wm = wid & 3;                       // warp row 0..3 -> rows wm*32
    int wn = wid >> 2;                      // warp col 0..1 -> cols wn*64
    int rowBase = blockIdx.x * BM;
    int colBase = blockIdx.y * BN;

    int tg = lane & 3;                      // thread-in-group
    int gp = lane >> 2;                     // group id (0..7)

    float acc[2][8][4];
#pragma unroll
    for (int mt = 0; mt < 2; mt++)
#pragma unroll
        for (int nt = 0; nt < 8; nt++)
#pragma unroll
            for (int r = 0; r < 4; r++) acc[mt][nt][r] = 0.f;

    // global-load register staging
    float4 xv[2], wv[2];
    // X: f4 id e = tid + j*256 : row = e>>2, kq = (e&3)*4
    int xrow[2], xkq[2];
    // W: f4 id e = tid + j*256 : kk = e>>5, c4 = (e&31)*4
    int wkk[2], wc4[2];
#pragma unroll
    for (int j = 0; j < 2; j++) {
        int e = tid + j * 256;
        xrow[j] = e >> 2;  xkq[j] = (e & 3) * 4;
        wkk[j]  = e >> 5;  wc4[j] = (e & 31) * 4;
    }
    int grow[2];
#pragma unroll
    for (int j = 0; j < 2; j++) {
        int r = rowBase + xrow[j];
        grow[j] = r < NN ? r : NN - 1;      // clamp (tail block)
    }

    // ---- load stage 0
#pragma unroll
    for (int j = 0; j < 2; j++) {
        xv[j] = *(const float4*)(x + (size_t)grow[j] * FD + xkq[j]);
        wv[j] = *(const float4*)(W1 + (size_t)wkk[j] * HD + colBase + wc4[j]);
    }
#pragma unroll
    for (int j = 0; j < 2; j++) {
        Xs[0][xrow[j]][xkq[j] + 0] = f2tf(xv[j].x);
        Xs[0][xrow[j]][xkq[j] + 1] = f2tf(xv[j].y);
        Xs[0][xrow[j]][xkq[j] + 2] = f2tf(xv[j].z);
        Xs[0][xrow[j]][xkq[j] + 3] = f2tf(xv[j].w);
        Ws[0][wkk[j]][wc4[j] + 0] = f2tf(wv[j].x);
        Ws[0][wkk[j]][wc4[j] + 1] = f2tf(wv[j].y);
        Ws[0][wkk[j]][wc4[j] + 2] = f2tf(wv[j].z);
        Ws[0][wkk[j]][wc4[j] + 3] = f2tf(wv[j].w);
    }
    __syncthreads();

#pragma unroll
    for (int kc = 0; kc < FD / BK; kc++) {
        int s = kc & 1;
        if (kc + 1 < FD / BK) {
            int k0 = (kc + 1) * BK;
#pragma unroll
            for (int j = 0; j < 2; j++) {
                xv[j] = *(const float4*)(x + (size_t)grow[j] * FD + k0 + xkq[j]);
                wv[j] = *(const float4*)(W1 + (size_t)(k0 + wkk[j]) * HD + colBase + wc4[j]);
            }
        }
        // ---- compute on stage s
#pragma unroll
        for (int ks = 0; ks < 2; ks++) {
            int kb = ks * 8;
            unsigned a[2][4];
#pragma unroll
            for (int mt = 0; mt < 2; mt++) {
                int r = wm * 32 + mt * 16 + gp;
                a[mt][0] = Xs[s][r][kb + tg];
                a[mt][1] = Xs[s][r + 8][kb + tg];
                a[mt][2] = Xs[s][r][kb + tg + 4];
                a[mt][3] = Xs[s][r + 8][kb + tg + 4];
            }
#pragma unroll
            for (int nt = 0; nt < 8; nt++) {
                int c = wn * 64 + nt * 8 + gp;
                unsigned b0 = Ws[s][kb + tg][c];
                unsigned b1v = Ws[s][kb + tg + 4][c];
                mma_tf32(acc[0][nt], a[0], b0, b1v);
                mma_tf32(acc[1][nt], a[1], b0, b1v);
            }
        }
        if (kc + 1 < FD / BK) {
            int ns = 1 - s;
#pragma unroll
            for (int j = 0; j < 2; j++) {
                Xs[ns][xrow[j]][xkq[j] + 0] = f2tf(xv[j].x);
                Xs[ns][xrow[j]][xkq[j] + 1] = f2tf(xv[j].y);
                Xs[ns][xrow[j]][xkq[j] + 2] = f2tf(xv[j].z);
                Xs[ns][xrow[j]][xkq[j] + 3] = f2tf(xv[j].w);
                Ws[ns][wkk[j]][wc4[j] + 0] = f2tf(wv[j].x);
                Ws[ns][wkk[j]][wc4[j] + 1] = f2tf(wv[j].y);
                Ws[ns][wkk[j]][wc4[j] + 2] = f2tf(wv[j].z);
                Ws[ns][wkk[j]][wc4[j] + 3] = f2tf(wv[j].w);
            }
        }
        __syncthreads();
    }

    // ---- epilogue: bias + relu + atomic scatter into g_agg
    float bias[8][2];
#pragma unroll
    for (int nt = 0; nt < 8; nt++) {
        int c = colBase + wn * 64 + nt * 8 + 2 * tg;
        bias[nt][0] = __ldg(b1 + c);
        bias[nt][1] = __ldg(b1 + c + 1);
    }
#pragma unroll
    for (int mt = 0; mt < 2; mt++) {
#pragma unroll
        for (int ro = 0; ro < 2; ro++) {
            int m = rowBase + wm * 32 + mt * 16 + gp + ro * 8;
            if (m < NN) {
                int mp = g_mapped[m];
                float* dst = g_agg + (size_t)mp * HD;
#pragma unroll
                for (int nt = 0; nt < 8; nt++) {
                    int c = colBase + wn * 64 + nt * 8 + 2 * tg;
                    float v0 = acc[mt][nt][ro * 2 + 0] + bias[nt][0];
                    float v1 = acc[mt][nt][ro * 2 + 1] + bias[nt][1];
                    v0 = v0 > 0.f ? v0 : 0.f;
                    v1 = v1 > 0.f ? v1 : 0.f;
                    atomicAdd(dst + c, v0);
                    atomicAdd(dst + c + 1, v1);
                }
            }
        }
    }
}

// ---------------- GEMM2: out = relu(agg) @ W2 + b2 --------------------------
// block 256 thr, tile 256 rows x 40 cols, K chunks of 16, cp.async double-buf.
#define G2R 256
#define AS_S 20
__global__ void __launch_bounds__(256) k_gemm2(
    const float* __restrict__ W2, const float* __restrict__ b2,
    float* __restrict__ out)
{
    __shared__ float As[2][G2R][AS_S];      // 40960 B
    __shared__ float W2c[2][16][44];        //  5632 B
    int tid = threadIdx.x;
    int tx = tid & 7;                       // cols tx*5 .. tx*5+4
    int ty = tid >> 3;                      // rows ty + 32*r, r<8
    int row0 = blockIdx.x * G2R;

    unsigned asBase = (unsigned)__cvta_generic_to_shared(&As[0][0][0]);
    unsigned wcBase = (unsigned)__cvta_generic_to_shared(&W2c[0][0][0]);

    // prefetch indices
    int arow[4], akq[4];
#pragma unroll
    for (int j = 0; j < 4; j++) {
        int e = tid + j * 256;              // f4 id in [0,1024)
        arow[j] = e >> 2; akq[j] = (e & 3) * 4;
    }
    int gr[4];
#pragma unroll
    for (int j = 0; j < 4; j++) {
        int r = row0 + arow[j];
        gr[j] = r < NN ? r : NN - 1;
    }
    int we = tid;                            // W2 chunk f4 id in [0,160)
    int wk = we / 10, wc4 = (we % 10) * 4;

    auto prefetch = [&](int c, int s) {
#pragma unroll
        for (int j = 0; j < 4; j++) {
            unsigned dst = asBase + ((s * G2R + arow[j]) * AS_S + akq[j]) * 4;
            cp_async16(dst, g_agg + (size_t)gr[j] * HD + c * 16 + akq[j]);
        }
        if (we < 160) {
            unsigned dst = wcBase + ((s * 16 + wk) * 44 + wc4) * 4;
            cp_async16(dst, W2 + (size_t)(c * 16 + wk) * CD + wc4);
        }
        cp_commit();
    };

    float acc[8][5];
#pragma unroll
    for (int r = 0; r < 8; r++)
#pragma unroll
        for (int j = 0; j < 5; j++) acc[r][j] = 0.f;

    prefetch(0, 0);
#pragma unroll
    for (int c = 0; c < HD / 16; c++) {
        int s = c & 1;
        if (c + 1 < HD / 16) {
            prefetch(c + 1, 1 - s);
            cp_wait<1>();
        } else {
            cp_wait<0>();
        }
        __syncthreads();
#pragma unroll
        for (int k = 0; k < 16; k++) {
            float a[8], w[5];
#pragma unroll
            for (int r = 0; r < 8; r++)
                a[r] = fmaxf(As[s][ty + 32 * r][k], 0.f);
#pragma unroll
            for (int j = 0; j < 5; j++)
                w[j] = W2c[s][k][tx * 5 + j];
#pragma unroll
            for (int r = 0; r < 8; r++)
#pragma unroll
                for (int j = 0; j < 5; j++)
                    acc[r][j] = fmaf(a[r], w[j], acc[r][j]);
        }
        __syncthreads();
    }

    float bb[5];
#pragma unroll
    for (int j = 0; j < 5; j++) bb[j] = b2[tx * 5 + j];
#pragma unroll
    for (int r = 0; r < 8; r++) {
        int row = row0 + ty + 32 * r;
        if (row < NN) {
#pragma unroll
            for (int j = 0; j < 5; j++)
                out[(size_t)row * CD + tx * 5 + j] = acc[r][j] + bb[j];
        }
    }
}

// ---------------- launch -----------------------------------------------------
extern "C" void kernel_launch(void* const* d_in, const int* in_sizes, int n_in,
                              void* d_out, int out_size) {
    const float* x    = (const float*)d_in[0];
    const int*   edge = (const int*)d_in[1];
    const float* W1   = (const float*)d_in[2];
    const float* b1   = (const float*)d_in[3];
    const float* W2   = (const float*)d_in[4];
    const float* b2   = (const float*)d_in[5];
    float* out = (float*)d_out;

    int nb_elem = (NN + 255) / 256;          // 1954
    int nb_scan = (NN + 1023) / 1024;        // 489

    k_zero_agg<<<8192, 256>>>();
    k_init_first<<<nb_elem, 256>>>();
    k_firstpos<<<nb_elem, 256>>>(edge);
    k_scan1<<<nb_scan, 256>>>(edge);
    k_scan2<<<1, 512>>>(nb_scan);
    k_scan3<<<nb_scan, 256>>>(edge);
    k_mapped<<<nb_elem, 256>>>(edge);

    dim3 g1((NN + BM - 1) / BM, HD / BN);    // 3907 x 2
    k_gemm1_mma<<<g1, 256>>>(x, W1, b1);

    int nb_g2 = (NN + G2R - 1) / G2R;        // 1954
    k_gemm2<<<nb_g2, 256>>>(W2, b2, out);
}